// round 2
// baseline (speedup 1.0000x reference)
#include <cuda_runtime.h>
#include <cuda_bf16.h>

#define NUM_CHIPS 4
#define N_EXPERTS 32
#define TOP_K 4
#define SEQ 1024
#define HIDDEN 2048
#define MAX_TOK 1024
#define META_LEN 8
#define NPC (SEQ * TOP_K)            /* 4096 assignments per chip  */
#define NA (NUM_CHIPS * NPC)         /* 16384 total assignments    */
#define NROWS (N_EXPERTS * MAX_TOK)  /* 32768 output rows          */
#define RANK_THREADS 128
#define CHUNK 32                     /* NPC / RANK_THREADS         */

#define COPY_BLOCKS 2048
#define COPY_THREADS 256
#define V4_PER_ROW (HIDDEN / 4)      /* 512 */
#define TOTAL_V4 ((long)NROWS * V4_PER_ROW)          /* 16777216 */
#define COPY_STRIDE (COPY_BLOCKS * COPY_THREADS)     /* 524288   */
#define COPY_TRIPS (TOTAL_V4 / COPY_STRIDE)          /* 32       */

/* scratch — no allocations allowed */
__device__ int g_total[N_EXPERTS];
__device__ int g_row[NA];        /* assignment -> destination row          */
__device__ int g_srcrow[NROWS];  /* row -> source token row index, or -1   */

/* ------------------------------------------------------------------ */
/* Kernel 1: full dispatch plan in ONE block (512 thr = 4 chips x 128).
   u16 histograms: [chip][expert][thread] = 32 KB smem.
   Stable (token, topk) order preserved: thread lt owns the contiguous
   chunk [lt*32, lt*32+32) and the prefix walks threads in order.       */
__global__ void __launch_bounds__(512) k_plan(const int* __restrict__ indices,
                                              float* __restrict__ out_cnt) {
    __shared__ unsigned short hist[NUM_CHIPS * N_EXPERTS * RANK_THREADS]; /* 32 KB */
    __shared__ int s_counts[NUM_CHIPS * N_EXPERTS];
    __shared__ int s_choff[NUM_CHIPS * N_EXPERTS];

    const int t  = threadIdx.x;
    const int c  = t >> 7;          /* chip     */
    const int lt = t & 127;         /* lane in chip group */

    const int* p = indices + c * NPC + lt * CHUNK;
    int e_loc[CHUNK];
#pragma unroll 8
    for (int i = 0; i < CHUNK; i++) e_loc[i] = p[i];

    unsigned short* h = hist + c * N_EXPERTS * RANK_THREADS;
#pragma unroll
    for (int e = 0; e < N_EXPERTS; e++) h[e * RANK_THREADS + lt] = 0;
#pragma unroll 8
    for (int i = 0; i < CHUNK; i++) h[e_loc[i] * RANK_THREADS + lt]++;
    __syncthreads();

    /* exclusive prefix across the 128 chunks, one thread per (chip,expert) */
    if (t < NUM_CHIPS * N_EXPERTS) {
        const int cc = t >> 5, e = t & 31;
        unsigned short* hh = hist + (cc * N_EXPERTS + e) * RANK_THREADS;
        int sum = 0;
        for (int j = 0; j < RANK_THREADS; j++) {
            int v = hh[j]; hh[j] = (unsigned short)sum; sum += v;
        }
        s_counts[cc * N_EXPERTS + e] = sum;
    }
    __syncthreads();

    /* cross-chip exclusive cumsum -> chip offsets, totals, counters out */
    if (t < N_EXPERTS) {
        int off = 0;
#pragma unroll
        for (int cc = 0; cc < NUM_CHIPS; cc++) {
            s_choff[cc * N_EXPERTS + t] = off;
            off += s_counts[cc * N_EXPERTS + t];
        }
        g_total[t] = off;
        out_cnt[t] = (float)off;
    }
    __syncthreads();

    /* stable rank -> final destination row per assignment */
    const int base = c * NPC + lt * CHUNK;
#pragma unroll 8
    for (int i = 0; i < CHUNK; i++) {
        const int e = e_loc[i];
        const int r = h[e * RANK_THREADS + lt]++;
        g_row[base + i] = e * MAX_TOK + s_choff[c * N_EXPERTS + e] + r;
    }
}

/* ------------------------------------------------------------------ */
/* Kernel 2: build row->src table + all metadata.
   Threads [0,16384): assignment role (filled rows).
   Threads [16384,49152): row role (tail rows -> -1).                  */
__global__ void __launch_bounds__(256) k_prep(const float* __restrict__ w,
                                              float* __restrict__ meta) {
    const int t = blockIdx.x * 256 + threadIdx.x;
    if (t < NA) {
        const int row = g_row[t];
        const int c = t >> 12, n = t & (NPC - 1);
        const int tok = n >> 2, kk = n & (TOP_K - 1);
        const int e = row >> 10;
        g_srcrow[row] = c * SEQ + tok;
        __nv_bfloat16 wb = __float2bfloat16(w[t]);      /* RNE, matches jnp */
        const int bits = (int)__bfloat16_as_short(wb);  /* sign-extended    */
        float4* m = (float4*)(meta + (size_t)row * META_LEN);
        m[0] = make_float4((float)c, (float)tok, (float)kk, (float)e);
        m[1] = make_float4((float)bits, 0.f, 0.f, 0.f);
    } else {
        const int row = t - NA;
        if (row >= NROWS) return;
        const int e = row >> 10, r = row & (MAX_TOK - 1);
        if (r < g_total[e]) return;                     /* filled, handled above */
        g_srcrow[row] = -1;
        float4* m = (float4*)(meta + (size_t)row * META_LEN);
        const float4 neg = make_float4(-1.f, -1.f, -1.f, -1.f);
        m[0] = neg; m[1] = neg;
    }
}

/* ------------------------------------------------------------------ */
/* Kernel 3: single streaming pass producing the whole 256 MB buffer.
   Flat float4 index; row = i>>9 (warp-uniform lookup, L1-hot).
   Unroll-4 -> 4 independent load chains per warp for deep MLP.        */
__global__ void __launch_bounds__(COPY_THREADS) k_copy(const float4* __restrict__ x4,
                                                       float4* __restrict__ buf4) {
    const unsigned tid = blockIdx.x * COPY_THREADS + threadIdx.x;
#pragma unroll 4
    for (int it = 0; it < COPY_TRIPS; it++) {
        const long i = (long)it * COPY_STRIDE + tid;
        const int row = (int)(i >> 9);
        const int off = (int)(i & (V4_PER_ROW - 1));
        const int s = __ldg(&g_srcrow[row]);
        float4 v = make_float4(0.f, 0.f, 0.f, 0.f);
        if (s >= 0) v = __ldg(&x4[(long)s * V4_PER_ROW + off]);
        buf4[i] = v;
    }
}

/* ------------------------------------------------------------------ */
extern "C" void kernel_launch(void* const* d_in, const int* in_sizes, int n_in,
                              void* d_out, int out_size) {
    const float* x   = (const float*)d_in[0];
    const float* w   = (const float*)d_in[1];
    const int*   idx = (const int*)d_in[2];

    float* out  = (float*)d_out;
    float* buf  = out;                                                   /* 32*1024*2048 */
    float* meta = out + (size_t)NROWS * HIDDEN;                          /* 32*1024*8    */
    float* cnt  = meta + (size_t)NROWS * META_LEN;                       /* 32           */

    k_plan<<<1, 512>>>(idx, cnt);
    k_prep<<<(NA + NROWS + 255) / 256, 256>>>(w, meta);
    k_copy<<<COPY_BLOCKS, COPY_THREADS>>>((const float4*)x, (float4*)buf);
}

// round 3
// speedup vs baseline: 1.2595x; 1.2595x over previous
#include <cuda_runtime.h>
#include <cuda_bf16.h>

#define NUM_CHIPS 4
#define N_EXPERTS 32
#define TOP_K 4
#define SEQ 1024
#define HIDDEN 2048
#define MAX_TOK 1024
#define META_LEN 8
#define NPC (SEQ * TOP_K)            /* 4096 assignments per chip  */
#define NA (NUM_CHIPS * NPC)         /* 16384 total assignments    */
#define NROWS (N_EXPERTS * MAX_TOK)  /* 32768 output rows          */

#define COPY_BLOCKS 2048
#define COPY_THREADS 256
#define V4_PER_ROW (HIDDEN / 4)      /* 512 */
#define TOTAL_V4 ((long)NROWS * V4_PER_ROW)          /* 16777216 */
#define COPY_STRIDE (COPY_BLOCKS * COPY_THREADS)     /* 524288   */
#define COPY_TRIPS (TOTAL_V4 / COPY_STRIDE)          /* 32       */

/* scratch — no allocations allowed */
__device__ int g_counts[NUM_CHIPS * N_EXPERTS];
__device__ int g_choff[NUM_CHIPS * N_EXPERTS];
__device__ int g_total[N_EXPERTS];
__device__ int g_rank[NA];       /* assignment -> stable rank within its chip+expert */
__device__ int g_srcrow[NROWS];  /* row -> source token row index, or -1             */

/* ------------------------------------------------------------------ */
/* Kernel 1: stable within-chip rank via warp intrinsics.
   One block per chip, 1024 threads; warp w owns assignments
   [w*128, w*128+128) in 4 rounds of 32 (lane order = flat order).
   match_any + lane-prefix gives stable rank; smem wcount accumulates
   across rounds; warp-per-expert shuffle scan gives warp offsets.      */
__global__ void __launch_bounds__(1024) k_rank(const int* __restrict__ indices) {
    __shared__ int wcount[32 * 33];   /* [warp][expert], 33-padded */
    __shared__ int woff[32 * 33];
    const int c = blockIdx.x;
    const int tid = threadIdx.x, w = tid >> 5, lane = tid & 31;

    for (int i = tid; i < 32 * 33; i += 1024) wcount[i] = 0;
    __syncthreads();

    int er[4], lr[4];
#pragma unroll
    for (int r = 0; r < 4; r++) {
        const int j = w * 128 + r * 32 + lane;          /* coalesced */
        const int e = indices[c * NPC + j];
        const unsigned mask = __match_any_sync(0xffffffffu, e);
        const int leader = __ffs(mask) - 1;
        const int prefix = __popc(mask & ((1u << lane) - 1u));
        int base = 0;
        if (lane == leader) base = atomicAdd(&wcount[w * 33 + e], __popc(mask));
        base = __shfl_sync(0xffffffffu, base, leader);
        er[r] = e; lr[r] = base + prefix;
    }
    __syncthreads();

    /* warp e scans wcount[*][e] across the 32 warps (lane = warp idx) */
    {
        const int e = w;
        const int val = wcount[lane * 33 + e];
        int incl = val;
#pragma unroll
        for (int d = 1; d < 32; d <<= 1) {
            int n = __shfl_up_sync(0xffffffffu, incl, d);
            if (lane >= d) incl += n;
        }
        woff[lane * 33 + e] = incl - val;
        if (lane == 31) g_counts[c * N_EXPERTS + e] = incl;
    }
    __syncthreads();

#pragma unroll
    for (int r = 0; r < 4; r++) {
        const int j = w * 128 + r * 32 + lane;
        g_rank[c * NPC + j] = woff[w * 33 + er[r]] + lr[r];
    }
}

/* ------------------------------------------------------------------ */
/* Kernel 2: cross-chip exclusive cumsum -> chip offsets, totals,
   counters output section.                                            */
__global__ void k_offsets(float* __restrict__ out_cnt) {
    const int e = threadIdx.x;  /* 32 threads */
    int off = 0;
#pragma unroll
    for (int c = 0; c < NUM_CHIPS; c++) {
        g_choff[c * N_EXPERTS + e] = off;
        off += g_counts[c * N_EXPERTS + e];
    }
    g_total[e] = off;
    out_cnt[e] = (float)off;
}

/* ------------------------------------------------------------------ */
/* Kernel 3: build row->src table + all metadata.
   Threads [0,16384): assignment role (filled rows).
   Threads [16384,49152): row role (tail rows -> -1).                  */
__global__ void __launch_bounds__(256) k_prep(const float* __restrict__ w,
                                              const int* __restrict__ indices,
                                              float* __restrict__ meta) {
    const int t = blockIdx.x * 256 + threadIdx.x;
    if (t < NA) {
        const int c = t >> 12, n = t & (NPC - 1);
        const int tok = n >> 2, kk = n & (TOP_K - 1);
        const int e = indices[t];                        /* coalesced */
        const int row = e * MAX_TOK + g_choff[c * N_EXPERTS + e] + g_rank[t];
        g_srcrow[row] = c * SEQ + tok;
        __nv_bfloat16 wb = __float2bfloat16(w[t]);      /* RNE, matches jnp */
        const int bits = (int)__bfloat16_as_short(wb);  /* sign-extended    */
        float4* m = (float4*)(meta + (size_t)row * META_LEN);
        m[0] = make_float4((float)c, (float)tok, (float)kk, (float)e);
        m[1] = make_float4((float)bits, 0.f, 0.f, 0.f);
    } else {
        const int row = t - NA;
        if (row >= NROWS) return;
        const int e = row >> 10, r = row & (MAX_TOK - 1);
        if (r < g_total[e]) return;                      /* filled above */
        g_srcrow[row] = -1;
        float4* m = (float4*)(meta + (size_t)row * META_LEN);
        const float4 neg = make_float4(-1.f, -1.f, -1.f, -1.f);
        m[0] = neg; m[1] = neg;
    }
}

/* ------------------------------------------------------------------ */
/* Kernel 4: single streaming pass producing the whole 256 MB buffer.
   Flat float4 index; row = i>>9 (warp-uniform lookup, L1-hot).
   Unroll-4 -> 4 independent load chains; streaming stores keep the
   32 MB x working set resident in L2.                                 */
__global__ void __launch_bounds__(COPY_THREADS) k_copy(const float4* __restrict__ x4,
                                                       float4* __restrict__ buf4) {
    const unsigned tid = blockIdx.x * COPY_THREADS + threadIdx.x;
#pragma unroll 4
    for (int it = 0; it < COPY_TRIPS; it++) {
        const long i = (long)it * COPY_STRIDE + tid;
        const int row = (int)(i >> 9);
        const int off = (int)(i & (V4_PER_ROW - 1));
        const int s = __ldg(&g_srcrow[row]);
        float4 v = make_float4(0.f, 0.f, 0.f, 0.f);
        if (s >= 0) v = __ldg(&x4[(long)s * V4_PER_ROW + off]);
        __stcs(&buf4[i], v);
    }
}

/* ------------------------------------------------------------------ */
extern "C" void kernel_launch(void* const* d_in, const int* in_sizes, int n_in,
                              void* d_out, int out_size) {
    const float* x   = (const float*)d_in[0];
    const float* w   = (const float*)d_in[1];
    const int*   idx = (const int*)d_in[2];

    float* out  = (float*)d_out;
    float* buf  = out;                                                   /* 32*1024*2048 */
    float* meta = out + (size_t)NROWS * HIDDEN;                          /* 32*1024*8    */
    float* cnt  = meta + (size_t)NROWS * META_LEN;                       /* 32           */

    k_rank<<<NUM_CHIPS, 1024>>>(idx);
    k_offsets<<<1, N_EXPERTS>>>(cnt);
    k_prep<<<(NA + NROWS + 255) / 256, 256>>>(w, idx, meta);
    k_copy<<<COPY_BLOCKS, COPY_THREADS>>>((const float4*)x, (float4*)buf);
}

// round 4
// speedup vs baseline: 1.5451x; 1.2267x over previous
#include <cuda_runtime.h>
#include <cuda_bf16.h>

#define NUM_CHIPS 4
#define N_EXPERTS 32
#define TOP_K 4
#define SEQ 1024
#define HIDDEN 2048
#define MAX_TOK 1024
#define META_LEN 8
#define NPC (SEQ * TOP_K)            /* 4096 assignments per chip  */
#define NA (NUM_CHIPS * NPC)         /* 16384 total assignments    */
#define NROWS (N_EXPERTS * MAX_TOK)  /* 32768 output rows          */

#define COPY_BLOCKS 2048
#define COPY_THREADS 256
#define V4_PER_ROW (HIDDEN / 4)      /* 512 */
#define COPY_STRIDE (COPY_BLOCKS * COPY_THREADS)     /* 524288 */
#define COPY_TRIPS 32                                /* 16M / 524288 */
#define UNROLL 8

/* scratch — no allocations allowed */
__device__ int g_counts[NUM_CHIPS * N_EXPERTS];
__device__ int g_rank[NA];       /* assignment -> stable rank within its chip+expert */
__device__ int g_srcrow[NROWS];  /* row -> source token row index, or -1             */

/* ------------------------------------------------------------------ */
/* Kernel 1: stable within-chip rank via warp intrinsics.
   One block per chip, 1024 threads; warp w owns assignments
   [w*128, w*128+128) in 4 rounds of 32 (lane order = flat order).      */
__global__ void __launch_bounds__(1024) k_rank(const int* __restrict__ indices) {
    __shared__ int wcount[32 * 33];   /* [warp][expert], 33-padded */
    __shared__ int woff[32 * 33];
    const int c = blockIdx.x;
    const int tid = threadIdx.x, w = tid >> 5, lane = tid & 31;

    for (int i = tid; i < 32 * 33; i += 1024) wcount[i] = 0;
    __syncthreads();

    int er[4], lr[4];
#pragma unroll
    for (int r = 0; r < 4; r++) {
        const int j = w * 128 + r * 32 + lane;          /* coalesced */
        const int e = indices[c * NPC + j];
        const unsigned mask = __match_any_sync(0xffffffffu, e);
        const int leader = __ffs(mask) - 1;
        const int prefix = __popc(mask & ((1u << lane) - 1u));
        int base = 0;
        if (lane == leader) base = atomicAdd(&wcount[w * 33 + e], __popc(mask));
        base = __shfl_sync(0xffffffffu, base, leader);
        er[r] = e; lr[r] = base + prefix;
    }
    __syncthreads();

    /* warp e scans wcount[*][e] across the 32 warps (lane = warp idx) */
    {
        const int e = w;
        const int val = wcount[lane * 33 + e];
        int incl = val;
#pragma unroll
        for (int d = 1; d < 32; d <<= 1) {
            int n = __shfl_up_sync(0xffffffffu, incl, d);
            if (lane >= d) incl += n;
        }
        woff[lane * 33 + e] = incl - val;
        if (lane == 31) g_counts[c * N_EXPERTS + e] = incl;
    }
    __syncthreads();

#pragma unroll
    for (int r = 0; r < 4; r++) {
        const int j = w * 128 + r * 32 + lane;
        g_rank[c * NPC + j] = woff[w * 33 + er[r]] + lr[r];
    }
}

/* ------------------------------------------------------------------ */
/* Kernel 2: offsets (inline) + row->src table + metadata + counters.
   Threads [0,16384): assignment role (filled rows).
   Threads [16384,49152): row role (tail rows -> -1).
   Threads [0,32): also emit experts_counter.                          */
__global__ void __launch_bounds__(256) k_prep(const float* __restrict__ w,
                                              const int* __restrict__ indices,
                                              float* __restrict__ meta,
                                              float* __restrict__ out_cnt) {
    const int t = blockIdx.x * 256 + threadIdx.x;
    if (t < NA) {
        const int c = t >> 12, n = t & (NPC - 1);
        const int tok = n >> 2, kk = n & (TOP_K - 1);
        const int e = indices[t];                        /* coalesced */
        int off = 0;
#pragma unroll
        for (int cc = 0; cc < NUM_CHIPS - 1; cc++)
            if (cc < c) off += g_counts[cc * N_EXPERTS + e];
        const int row = e * MAX_TOK + off + g_rank[t];
        g_srcrow[row] = c * SEQ + tok;
        __nv_bfloat16 wb = __float2bfloat16(w[t]);      /* RNE, matches jnp */
        const int bits = (int)__bfloat16_as_short(wb);  /* sign-extended    */
        float4* m = (float4*)(meta + (size_t)row * META_LEN);
        m[0] = make_float4((float)c, (float)tok, (float)kk, (float)e);
        m[1] = make_float4((float)bits, 0.f, 0.f, 0.f);
        if (t < N_EXPERTS) {                             /* counters section */
            int tot = 0;
#pragma unroll
            for (int cc = 0; cc < NUM_CHIPS; cc++) tot += g_counts[cc * N_EXPERTS + t];
            out_cnt[t] = (float)tot;
        }
    } else {
        const int row = t - NA;
        if (row >= NROWS) return;
        const int e = row >> 10, r = row & (MAX_TOK - 1);
        int tot = 0;
#pragma unroll
        for (int cc = 0; cc < NUM_CHIPS; cc++) tot += g_counts[cc * N_EXPERTS + e];
        if (r < tot) return;                             /* filled above */
        g_srcrow[row] = -1;
        float4* m = (float4*)(meta + (size_t)row * META_LEN);
        const float4 neg = make_float4(-1.f, -1.f, -1.f, -1.f);
        m[0] = neg; m[1] = neg;
    }
}

/* ------------------------------------------------------------------ */
/* Kernel 3: single streaming pass producing the whole 256 MB buffer.
   32-bit flat float4 index; row = i>>9 (warp-uniform, L1-hot).
   Software-pipelined unroll-8: 8 independent load chains, then the
   8 stores. Plain write-back stores (evict-first regressed in R3).    */
__global__ void __launch_bounds__(COPY_THREADS) k_copy(const float4* __restrict__ x4,
                                                       float4* __restrict__ buf4) {
    const unsigned tid = blockIdx.x * COPY_THREADS + threadIdx.x;
#pragma unroll
    for (int it = 0; it < COPY_TRIPS; it += UNROLL) {
        unsigned i[UNROLL]; int s[UNROLL]; float4 v[UNROLL];
#pragma unroll
        for (int u = 0; u < UNROLL; u++) {
            i[u] = (unsigned)(it + u) * COPY_STRIDE + tid;
            s[u] = __ldg(&g_srcrow[i[u] >> 9]);
        }
#pragma unroll
        for (int u = 0; u < UNROLL; u++) {
            v[u] = make_float4(0.f, 0.f, 0.f, 0.f);
            if (s[u] >= 0)
                v[u] = __ldg(&x4[(unsigned)s[u] * V4_PER_ROW + (i[u] & (V4_PER_ROW - 1))]);
        }
#pragma unroll
        for (int u = 0; u < UNROLL; u++) buf4[i[u]] = v[u];
    }
}

/* ------------------------------------------------------------------ */
extern "C" void kernel_launch(void* const* d_in, const int* in_sizes, int n_in,
                              void* d_out, int out_size) {
    const float* x   = (const float*)d_in[0];
    const float* w   = (const float*)d_in[1];
    const int*   idx = (const int*)d_in[2];

    float* out  = (float*)d_out;
    float* buf  = out;                                                   /* 32*1024*2048 */
    float* meta = out + (size_t)NROWS * HIDDEN;                          /* 32*1024*8    */
    float* cnt  = meta + (size_t)NROWS * META_LEN;                       /* 32           */

    k_rank<<<NUM_CHIPS, 1024>>>(idx);
    k_prep<<<(NA + NROWS + 255) / 256, 256>>>(w, idx, meta, cnt);
    k_copy<<<COPY_BLOCKS, COPY_THREADS>>>((const float4*)x, (float4*)buf);
}